// round 6
// baseline (speedup 1.0000x reference)
#include <cuda_runtime.h>

// ---------------------------------------------------------------------------
// LCA layer on GB300.
//
// b = conv2d(x, D, s=4, p=2); 10x { inh = conv(convT(a)) - a;
//   u += 0.1*(b - u - inh); a = softshrink(u, 0.1) }
//
// conv∘convT == Gram operator: 3x3 tap (stride-4, k=8 atoms overlap at
// |δ|<=1), G[t][n][m] 64x64 per tap, center diag -1 folded (the "-a").
// BOUNDARY: the outer conv zero-clamps recon outside [0,224): at edge output
// pixels, products with ky∈{0,1} (top), ky∈{6,7} (bot), kx∈{0,1}/{6,7}
// (left/right) must be EXCLUDED. Since a's halo is zero, the exclusion
// collapses to dy=0 (resp. dx=0) taps only -> 1-D 3-tap edge correction
// Grams CT/CB/CL/CR + 4 corner single-tap overlap matrices CO
// (inclusion-exclusion at corners).  lca_fix applies u += 0.1*corr and
// re-shrinks the border after each iteration.
// ---------------------------------------------------------------------------

#define NATOMS 64
#define BATCH  64
#define H 56
#define W 56
#define HW (H*W)
#define PLANE ((size_t)NATOMS * HW)

__device__ float g_B [BATCH * NATOMS * HW];
__device__ float g_U [BATCH * NATOMS * HW];
__device__ float g_A0[BATCH * NATOMS * HW];
__device__ float g_G [9 * 64 * 64];            // interior Gram [tap][n][m]
__device__ float g_CT[3 * 64 * 64];            // top edge, taps dx=-1,0,1
__device__ float g_CB[3 * 64 * 64];            // bottom
__device__ float g_CL[3 * 64 * 64];            // left,  taps dy=-1,0,1
__device__ float g_CR[3 * 64 * 64];            // right
__device__ float g_CO[4 * 64 * 64];            // corner overlaps TL,TR,BL,BR

// ---- packed f32x2 helpers --------------------------------------------------
__device__ __forceinline__ unsigned long long dup2(float x) {
    unsigned long long r;
    asm("mov.b64 %0, {%1, %1};" : "=l"(r) : "f"(x));
    return r;
}
__device__ __forceinline__ void ffma2(unsigned long long& d,
                                      unsigned long long a,
                                      unsigned long long b) {
    asm("fma.rn.f32x2 %0, %1, %2, %0;" : "+l"(d) : "l"(a), "l"(b));
}
__device__ __forceinline__ float2 unpk(unsigned long long v) {
    float2 r;
    asm("mov.b64 {%0, %1}, %2;" : "=f"(r.x), "=f"(r.y) : "l"(v));
    return r;
}
__device__ __forceinline__ float shrinkf(float u) {
    float mag = fabsf(u) - 0.1f;
    return mag > 0.0f ? copysignf(mag, u) : 0.0f;
}

// ---------------------------------------------------------------------------
// Gram kernel.  25 blocks: 0..8 interior taps, 9..20 edge (side*3+shift),
// 21..24 corner overlaps.
// ---------------------------------------------------------------------------
__global__ void lca_gram(const float* __restrict__ dict) {
    __shared__ float ds[64 * 3 * 8 * 8];        // 48 KB
    const int t   = blockIdx.x;
    const int tid = threadIdx.x;
    for (int e = tid; e < 12288; e += 256) ds[e] = dict[e];
    __syncthreads();

    if (t < 9) {
        const int dy = t / 3 - 1, dx = t % 3 - 1;
        const int kylo = dy < 0 ? 4 : 0, kyhi = dy > 0 ? 4 : 8;
        const int kxlo = dx < 0 ? 4 : 0, kxhi = dx > 0 ? 4 : 8;
        for (int e = tid; e < 4096; e += 256) {
            const int n = e >> 6, m = e & 63;
            float s = 0.0f;
            for (int i = 0; i < 3; ++i) {
                const float* dm = &ds[m * 192 + i * 64];
                const float* dn = &ds[n * 192 + i * 64 + 4 * dy * 8 + 4 * dx];
                for (int ky = kylo; ky < kyhi; ++ky)
                    #pragma unroll
                    for (int kx = kxlo; kx < kxhi; ++kx)
                        s += dm[ky * 8 + kx] * dn[ky * 8 + kx];
            }
            if (t == 4 && n == m) s -= 1.0f;
            g_G[t * 4096 + e] = s;
        }
    } else if (t < 21) {
        const int side = (t - 9) / 3;           // 0 top,1 bot,2 left,3 right
        const int j    = (t - 9) % 3;
        const int d    = j - 1;
        float* out = (side == 0 ? g_CT : side == 1 ? g_CB
                    : side == 2 ? g_CL : g_CR) + j * 4096;
        for (int e = tid; e < 4096; e += 256) {
            const int n = e >> 6, m = e & 63;
            float s = 0.0f;
            for (int i = 0; i < 3; ++i) {
                const float* dm = &ds[m * 192 + i * 64];
                const float* dn = &ds[n * 192 + i * 64];
                if (side < 2) {                 // excluded ky rows, dx shift
                    const int ky0 = (side == 0) ? 0 : 6;
                    const int kxlo = d < 0 ? 4 : 0, kxhi = d > 0 ? 4 : 8;
                    for (int ky = ky0; ky < ky0 + 2; ++ky)
                        for (int kx = kxlo; kx < kxhi; ++kx)
                            s += dm[ky * 8 + kx] * dn[ky * 8 + kx + 4 * d];
                } else {                        // excluded kx cols, dy shift
                    const int kx0 = (side == 2) ? 0 : 6;
                    const int kylo = d < 0 ? 4 : 0, kyhi = d > 0 ? 4 : 8;
                    for (int ky = kylo; ky < kyhi; ++ky)
                        for (int kx = kx0; kx < kx0 + 2; ++kx)
                            s += dm[ky * 8 + kx] * dn[(ky + 4 * d) * 8 + kx];
                }
            }
            out[e] = s;
        }
    } else {
        const int c   = t - 21;                 // 0 TL,1 TR,2 BL,3 BR
        const int ky0 = (c < 2) ? 0 : 6;
        const int kx0 = (c & 1) ? 6 : 0;
        for (int e = tid; e < 4096; e += 256) {
            const int n = e >> 6, m = e & 63;
            float s = 0.0f;
            for (int i = 0; i < 3; ++i) {
                const float* dm = &ds[m * 192 + i * 64];
                const float* dn = &ds[n * 192 + i * 64];
                for (int ky = ky0; ky < ky0 + 2; ++ky)
                    for (int kx = kx0; kx < kx0 + 2; ++kx)
                        s += dm[ky * 8 + kx] * dn[ky * 8 + kx];
            }
            g_CO[c * 4096 + e] = s;
        }
    }
}

// ---------------------------------------------------------------------------
// b = conv2d(x, D, 4, 2), fused iter 1: u1 = 0.1*b, a1 = shrink(u1). Exact
// everywhere (boundary handled by zero-padded x patch; a=0 => no Gram term).
// ---------------------------------------------------------------------------
__global__ __launch_bounds__(256, 2)
void lca_b(const float* __restrict__ x, const float* __restrict__ dict) {
    __shared__ float xs[36 * 37];
    __shared__ float dt[64 * 64];

    const int bi   = blockIdx.y;
    const int tile = blockIdx.x;
    const int ty0  = (tile / 7) * 8, tx0 = (tile % 7) * 8;
    const int tid  = threadIdx.x;
    const int pg   = tid & 15, cg = tid >> 4;
    const int py   = pg >> 1, px0 = (pg & 1) * 4;
    const int m0   = cg * 4;

    unsigned long long acc[4][2];
    #pragma unroll
    for (int j = 0; j < 4; ++j) { acc[j][0] = 0ull; acc[j][1] = 0ull; }

    for (int i = 0; i < 3; ++i) {
        __syncthreads();
        for (int e = tid; e < 4096; e += 256) {
            const int kk = e >> 6, m = e & 63;
            dt[kk * 64 + m] = dict[m * 192 + i * 64 + kk];
        }
        const int gy0 = 4 * ty0 - 2, gx0 = 4 * tx0 - 2;
        for (int e = tid; e < 1296; e += 256) {
            const int r = e / 36, cc = e % 36;
            const int gy = gy0 + r, gx = gx0 + cc;
            float v = 0.0f;
            if ((unsigned)gy < 224u && (unsigned)gx < 224u)
                v = x[((size_t)(bi * 3 + i) * 224 + gy) * 224 + gx];
            xs[r * 37 + cc] = v;
        }
        __syncthreads();

        for (int ky = 0; ky < 8; ++ky) {
            const float* xr = &xs[(4 * py + ky) * 37 + 4 * px0];
            const float* dk = &dt[(ky * 8) * 64 + m0];
            #pragma unroll
            for (int kx = 0; kx < 8; ++kx) {
                ulonglong2 g = *reinterpret_cast<const ulonglong2*>(dk + kx * 64);
                const unsigned long long d0 = dup2(xr[0  + kx]);
                const unsigned long long d1 = dup2(xr[4  + kx]);
                const unsigned long long d2 = dup2(xr[8  + kx]);
                const unsigned long long d3 = dup2(xr[12 + kx]);
                ffma2(acc[0][0], d0, g.x); ffma2(acc[0][1], d0, g.y);
                ffma2(acc[1][0], d1, g.x); ffma2(acc[1][1], d1, g.y);
                ffma2(acc[2][0], d2, g.x); ffma2(acc[2][1], d2, g.y);
                ffma2(acc[3][0], d3, g.x); ffma2(acc[3][1], d3, g.y);
            }
        }
    }

    const int y = ty0 + py;
    #pragma unroll
    for (int j = 0; j < 4; ++j) {
        const int xcol = tx0 + px0 + j;
        float bv[4];
        float2 p0 = unpk(acc[j][0]); bv[0] = p0.x; bv[1] = p0.y;
        float2 p1 = unpk(acc[j][1]); bv[2] = p1.x; bv[3] = p1.y;
        #pragma unroll
        for (int mm = 0; mm < 4; ++mm) {
            const size_t idx = ((size_t)(bi * 64 + m0 + mm) * H + y) * W + xcol;
            const float bb = bv[mm];
            const float un = 0.1f * bb;
            g_B[idx]  = bb;
            g_U[idx]  = un;
            g_A0[idx] = shrinkf(un);
        }
    }
}

// ---------------------------------------------------------------------------
// One LCA iteration (interior Gram everywhere; border fixed afterwards).
// ---------------------------------------------------------------------------
__global__ __launch_bounds__(256, 2)
void lca_iter(float* __restrict__ a_ext, int mode) {
    __shared__ float as[64 * 110];
    __shared__ float gs[64 * 64];

    const float* __restrict__ a_in  = mode ? a_ext : g_A0;
    float* __restrict__       a_out = mode ? g_A0  : a_ext;

    const int bi   = blockIdx.y;
    const int tile = blockIdx.x;
    const int ty0  = (tile / 7) * 8, tx0 = (tile % 7) * 8;
    const int tid  = threadIdx.x;

    const float* abase = a_in + (size_t)bi * PLANE;
    for (int e = tid; e < 6400; e += 256) {
        const int c  = e / 100;
        const int r  = (e / 10) % 10;
        const int cc = e % 10;
        const int gy = ty0 - 1 + r, gx = tx0 - 1 + cc;
        float v = 0.0f;
        if ((unsigned)gy < (unsigned)H && (unsigned)gx < (unsigned)W)
            v = abase[c * HW + gy * W + gx];
        as[c * 110 + r * 11 + cc] = v;
    }

    const int pg = tid & 15, cg = tid >> 4;
    const int py = pg >> 1, px0 = (pg & 1) * 4;
    const int m0 = cg * 4;

    unsigned long long acc[4][2];
    #pragma unroll
    for (int j = 0; j < 4; ++j) { acc[j][0] = 0ull; acc[j][1] = 0ull; }

    for (int tap = 0; tap < 9; ++tap) {
        __syncthreads();
        for (int e = tid; e < 4096; e += 256)
            gs[e] = g_G[tap * 4096 + e];
        __syncthreads();

        const int ty_ = tap / 3, tx_ = tap % 3;
        const float* ap = &as[(py + 2 - ty_) * 11 + (px0 + 2 - tx_)];
        const float* gp = &gs[m0];

        #pragma unroll 8
        for (int n = 0; n < 64; ++n) {
            ulonglong2 g = *reinterpret_cast<const ulonglong2*>(gp + n * 64);
            const float* an = ap + n * 110;
            const unsigned long long d0 = dup2(an[0]);
            const unsigned long long d1 = dup2(an[1]);
            const unsigned long long d2 = dup2(an[2]);
            const unsigned long long d3 = dup2(an[3]);
            ffma2(acc[0][0], d0, g.x); ffma2(acc[0][1], d0, g.y);
            ffma2(acc[1][0], d1, g.x); ffma2(acc[1][1], d1, g.y);
            ffma2(acc[2][0], d2, g.x); ffma2(acc[2][1], d2, g.y);
            ffma2(acc[3][0], d3, g.x); ffma2(acc[3][1], d3, g.y);
        }
    }

    const int y = ty0 + py;
    #pragma unroll
    for (int j = 0; j < 4; ++j) {
        const int xcol = tx0 + px0 + j;
        float ga[4];
        float2 p0 = unpk(acc[j][0]); ga[0] = p0.x; ga[1] = p0.y;
        float2 p1 = unpk(acc[j][1]); ga[2] = p1.x; ga[3] = p1.y;
        #pragma unroll
        for (int mm = 0; mm < 4; ++mm) {
            const size_t idx = ((size_t)(bi * 64 + m0 + mm) * H + y) * W + xcol;
            const float uo = g_U[idx];
            const float bv = g_B[idx];
            const float un = uo + 0.1f * (bv - uo - ga[mm]);
            g_U[idx]   = un;
            a_out[idx] = shrinkf(un);
        }
    }
}

// ---------------------------------------------------------------------------
// Border fix.  One block per image (no cross-block races). For each side:
// corr[m,pos] = sum_j sum_n C[side][j][n][m] * a[n, edge, pos-(j-1)];
// u += 0.1*corr.  Corners: u -= 0.1 * CO[c]·a (overlap double-count).
// Finally re-shrink a on all border pixels.
// ---------------------------------------------------------------------------
__global__ __launch_bounds__(256, 2)
void lca_fix(float* __restrict__ a_ext, int mode) {
    __shared__ unsigned long long cs[2048];     // C[j] as [n][m-pair]
    __shared__ float as2[64 * 58];              // edge line + halo

    const float* __restrict__ a_in  = mode ? a_ext : g_A0;
    float* __restrict__       a_out = mode ? g_A0  : a_ext;

    const int bi  = blockIdx.x;
    const int tid = threadIdx.x;
    const float* abase = a_in + (size_t)bi * PLANE;
    float*       ubase = g_U  + (size_t)bi * PLANE;
    const int mp   = tid >> 3;                  // 0..31 -> channels 2mp,2mp+1
    const int lane = tid & 7;

    for (int side = 0; side < 4; ++side) {
        __syncthreads();
        for (int e = tid; e < 64 * 58; e += 256) {
            const int n = e / 58, p = e % 58;
            const int pos = p - 1;
            float v = 0.0f;
            if ((unsigned)pos < 56u) {
                int y, x;
                if      (side == 0) { y = 0;   x = pos; }
                else if (side == 1) { y = 55;  x = pos; }
                else if (side == 2) { y = pos; x = 0;   }
                else                { y = pos; x = 55;  }
                v = abase[(n * 56 + y) * 56 + x];
            }
            as2[e] = v;
        }
        unsigned long long acc[7];
        #pragma unroll
        for (int g = 0; g < 7; ++g) acc[g] = 0ull;

        const float* C = (side == 0) ? g_CT : (side == 1) ? g_CB
                       : (side == 2) ? g_CL : g_CR;
        for (int j = 0; j < 3; ++j) {
            __syncthreads();
            const unsigned long long* Cj =
                reinterpret_cast<const unsigned long long*>(C + j * 4096);
            for (int e = tid; e < 2048; e += 256) cs[e] = Cj[e];
            __syncthreads();
            #pragma unroll
            for (int g = 0; g < 7; ++g) {
                const int pos = lane + 8 * g;
                const float* ap = &as2[pos + 2 - j];
                for (int n = 0; n < 64; ++n)
                    ffma2(acc[g], dup2(ap[n * 58]), cs[n * 32 + mp]);
            }
        }
        __syncthreads();
        #pragma unroll
        for (int g = 0; g < 7; ++g) {
            const int pos = lane + 8 * g;
            int y, x;
            if      (side == 0) { y = 0;   x = pos; }
            else if (side == 1) { y = 55;  x = pos; }
            else if (side == 2) { y = pos; x = 0;   }
            else                { y = pos; x = 55;  }
            float2 c2 = unpk(acc[g]);
            const int m = 2 * mp;
            const size_t i0 = ((size_t)m * 56 + y) * 56 + x;
            const size_t i1 = ((size_t)(m + 1) * 56 + y) * 56 + x;
            ubase[i0] += 0.1f * c2.x;
            ubase[i1] += 0.1f * c2.y;
        }
    }
    __syncthreads();

    // corner overlap subtraction (tap (0,0), both-excluded terms)
    {
        const int c = tid >> 6, m = tid & 63;
        const int yc = (c < 2) ? 0 : 55;
        const int xc = (c & 1) ? 55 : 0;
        float s = 0.0f;
        for (int n = 0; n < 64; ++n)
            s += g_CO[c * 4096 + n * 64 + m] * abase[(n * 56 + yc) * 56 + xc];
        ubase[((size_t)m * 56 + yc) * 56 + xc] -= 0.1f * s;
    }
    __syncthreads();

    // re-shrink all border pixels (corner duplicates write identical values)
    float* aobase = a_out + (size_t)bi * PLANE;
    for (int e = tid; e < 4 * 64 * 56; e += 256) {
        const int side = e / (64 * 56);
        const int r    = e % (64 * 56);
        const int m = r / 56, pos = r % 56;
        int y, x;
        if      (side == 0) { y = 0;   x = pos; }
        else if (side == 1) { y = 55;  x = pos; }
        else if (side == 2) { y = pos; x = 0;   }
        else                { y = pos; x = 55;  }
        const size_t idx = ((size_t)m * 56 + y) * 56 + x;
        aobase[idx] = shrinkf(ubase[idx]);
    }
}

// ---------------------------------------------------------------------------
extern "C" void kernel_launch(void* const* d_in, const int* in_sizes, int n_in,
                              void* d_out, int out_size) {
    (void)in_sizes; (void)n_in; (void)out_size;
    const float* x    = (const float*)d_in[0];
    const float* dict = (const float*)d_in[1];
    float*       out  = (float*)d_out;

    lca_gram<<<25, 256>>>(dict);
    lca_b<<<dim3(49, 64), 256>>>(x, dict);

    // iterations 2..10; odd count of lca_iter -> final a lands in d_out
    for (int it = 0; it < 9; ++it) {
        lca_iter<<<dim3(49, 64), 256>>>(out, it & 1);
        lca_fix<<<64, 256>>>(out, it & 1);
    }
}

// round 7
// speedup vs baseline: 1.1140x; 1.1140x over previous
#include <cuda_runtime.h>

// ---------------------------------------------------------------------------
// LCA layer on GB300.
//
// b = conv2d(x, D, s=4, p=2); 10x { inh = conv(convT(a)) - a;
//   u += 0.1*(b - u - inh); a = softshrink(u, 0.1) }
//
// conv∘convT == Gram operator: 3x3 taps (stride-4, k=8 atoms overlap |δ|<=1),
// G[t][n][m] 64x64 per tap, center diag -1 folded. Boundary: the outer conv
// zero-clamps recon outside the image; phantom products at edge pixels
// collapse to 1-D 3-tap edge Grams CT/CB/CL/CR + 4 corner overlaps CO
// (inclusion-exclusion). The border correction is FUSED into lca_iter
// (computed cooperatively from the halo smem, applied to ga pre-update).
//
// lca_iter: n-outer / tap-inner, a-halo stored f32x2-splatted in smem so the
// 3x6 a-patch loads as LDS.128 with no dup MOVs; G staged per 8-ch chunk as
// gs[n][tap][m]. 144 FFMA2 per n vs ~174 issue slots -> fma-pipe bound.
// ---------------------------------------------------------------------------

#define NATOMS 64
#define BATCH  64
#define H 56
#define W 56
#define HW (H*W)
#define PLANE ((size_t)NATOMS * HW)

__device__ float g_B [BATCH * NATOMS * HW];
__device__ float g_U [BATCH * NATOMS * HW];
__device__ float g_A0[BATCH * NATOMS * HW];
__device__ float g_G [9 * 64 * 64];            // interior Gram [tap][n][m]
__device__ float g_CT[3 * 64 * 64];            // top edge, taps dx=-1,0,1
__device__ float g_CB[3 * 64 * 64];            // bottom
__device__ float g_CL[3 * 64 * 64];            // left,  taps dy=-1,0,1
__device__ float g_CR[3 * 64 * 64];            // right
__device__ float g_CO[4 * 64 * 64];            // corner overlaps TL,TR,BL,BR

// ---- packed f32x2 helpers --------------------------------------------------
__device__ __forceinline__ unsigned long long dup2(float x) {
    unsigned long long r;
    asm("mov.b64 %0, {%1, %1};" : "=l"(r) : "f"(x));
    return r;
}
__device__ __forceinline__ void ffma2(unsigned long long& d,
                                      unsigned long long a,
                                      unsigned long long b) {
    asm("fma.rn.f32x2 %0, %1, %2, %0;" : "+l"(d) : "l"(a), "l"(b));
}
__device__ __forceinline__ float2 unpk(unsigned long long v) {
    float2 r;
    asm("mov.b64 {%0, %1}, %2;" : "=f"(r.x), "=f"(r.y) : "l"(v));
    return r;
}
__device__ __forceinline__ float shrinkf(float u) {
    float mag = fabsf(u) - 0.1f;
    return mag > 0.0f ? copysignf(mag, u) : 0.0f;
}

// ---------------------------------------------------------------------------
// Gram kernel. 25 blocks: 0..8 interior taps, 9..20 edges, 21..24 corners.
// ---------------------------------------------------------------------------
__global__ void lca_gram(const float* __restrict__ dict) {
    __shared__ float ds[64 * 3 * 8 * 8];
    const int t   = blockIdx.x;
    const int tid = threadIdx.x;
    for (int e = tid; e < 12288; e += 256) ds[e] = dict[e];
    __syncthreads();

    if (t < 9) {
        const int dy = t / 3 - 1, dx = t % 3 - 1;
        const int kylo = dy < 0 ? 4 : 0, kyhi = dy > 0 ? 4 : 8;
        const int kxlo = dx < 0 ? 4 : 0, kxhi = dx > 0 ? 4 : 8;
        for (int e = tid; e < 4096; e += 256) {
            const int n = e >> 6, m = e & 63;
            float s = 0.0f;
            for (int i = 0; i < 3; ++i) {
                const float* dm = &ds[m * 192 + i * 64];
                const float* dn = &ds[n * 192 + i * 64 + 4 * dy * 8 + 4 * dx];
                for (int ky = kylo; ky < kyhi; ++ky)
                    #pragma unroll
                    for (int kx = kxlo; kx < kxhi; ++kx)
                        s += dm[ky * 8 + kx] * dn[ky * 8 + kx];
            }
            if (t == 4 && n == m) s -= 1.0f;
            g_G[t * 4096 + e] = s;
        }
    } else if (t < 21) {
        const int side = (t - 9) / 3;           // 0 top,1 bot,2 left,3 right
        const int j    = (t - 9) % 3;
        const int d    = j - 1;
        float* out = (side == 0 ? g_CT : side == 1 ? g_CB
                    : side == 2 ? g_CL : g_CR) + j * 4096;
        for (int e = tid; e < 4096; e += 256) {
            const int n = e >> 6, m = e & 63;
            float s = 0.0f;
            for (int i = 0; i < 3; ++i) {
                const float* dm = &ds[m * 192 + i * 64];
                const float* dn = &ds[n * 192 + i * 64];
                if (side < 2) {
                    const int ky0 = (side == 0) ? 0 : 6;
                    const int kxlo = d < 0 ? 4 : 0, kxhi = d > 0 ? 4 : 8;
                    for (int ky = ky0; ky < ky0 + 2; ++ky)
                        for (int kx = kxlo; kx < kxhi; ++kx)
                            s += dm[ky * 8 + kx] * dn[ky * 8 + kx + 4 * d];
                } else {
                    const int kx0 = (side == 2) ? 0 : 6;
                    const int kylo = d < 0 ? 4 : 0, kyhi = d > 0 ? 4 : 8;
                    for (int ky = kylo; ky < kyhi; ++ky)
                        for (int kx = kx0; kx < kx0 + 2; ++kx)
                            s += dm[ky * 8 + kx] * dn[(ky + 4 * d) * 8 + kx];
                }
            }
            out[e] = s;
        }
    } else {
        const int c   = t - 21;
        const int ky0 = (c < 2) ? 0 : 6;
        const int kx0 = (c & 1) ? 6 : 0;
        for (int e = tid; e < 4096; e += 256) {
            const int n = e >> 6, m = e & 63;
            float s = 0.0f;
            for (int i = 0; i < 3; ++i) {
                const float* dm = &ds[m * 192 + i * 64];
                const float* dn = &ds[n * 192 + i * 64];
                for (int ky = ky0; ky < ky0 + 2; ++ky)
                    for (int kx = kx0; kx < kx0 + 2; ++kx)
                        s += dm[ky * 8 + kx] * dn[ky * 8 + kx];
            }
            g_CO[c * 4096 + e] = s;
        }
    }
}

// ---------------------------------------------------------------------------
// b = conv2d(x, D, 4, 2), fused iter 1: u1 = 0.1*b, a1 = shrink(u1).
// ---------------------------------------------------------------------------
__global__ __launch_bounds__(256, 2)
void lca_b(const float* __restrict__ x, const float* __restrict__ dict) {
    __shared__ float xs[36 * 37];
    __shared__ float dt[64 * 64];

    const int bi   = blockIdx.y;
    const int tile = blockIdx.x;
    const int ty0  = (tile / 7) * 8, tx0 = (tile % 7) * 8;
    const int tid  = threadIdx.x;
    const int pg   = tid & 15, cg = tid >> 4;
    const int py   = pg >> 1, px0 = (pg & 1) * 4;
    const int m0   = cg * 4;

    unsigned long long acc[4][2];
    #pragma unroll
    for (int j = 0; j < 4; ++j) { acc[j][0] = 0ull; acc[j][1] = 0ull; }

    for (int i = 0; i < 3; ++i) {
        __syncthreads();
        for (int e = tid; e < 4096; e += 256) {
            const int kk = e >> 6, m = e & 63;
            dt[kk * 64 + m] = dict[m * 192 + i * 64 + kk];
        }
        const int gy0 = 4 * ty0 - 2, gx0 = 4 * tx0 - 2;
        for (int e = tid; e < 1296; e += 256) {
            const int r = e / 36, cc = e % 36;
            const int gy = gy0 + r, gx = gx0 + cc;
            float v = 0.0f;
            if ((unsigned)gy < 224u && (unsigned)gx < 224u)
                v = x[((size_t)(bi * 3 + i) * 224 + gy) * 224 + gx];
            xs[r * 37 + cc] = v;
        }
        __syncthreads();

        for (int ky = 0; ky < 8; ++ky) {
            const float* xr = &xs[(4 * py + ky) * 37 + 4 * px0];
            const float* dk = &dt[(ky * 8) * 64 + m0];
            #pragma unroll
            for (int kx = 0; kx < 8; ++kx) {
                ulonglong2 g = *reinterpret_cast<const ulonglong2*>(dk + kx * 64);
                const unsigned long long d0 = dup2(xr[0  + kx]);
                const unsigned long long d1 = dup2(xr[4  + kx]);
                const unsigned long long d2 = dup2(xr[8  + kx]);
                const unsigned long long d3 = dup2(xr[12 + kx]);
                ffma2(acc[0][0], d0, g.x); ffma2(acc[0][1], d0, g.y);
                ffma2(acc[1][0], d1, g.x); ffma2(acc[1][1], d1, g.y);
                ffma2(acc[2][0], d2, g.x); ffma2(acc[2][1], d2, g.y);
                ffma2(acc[3][0], d3, g.x); ffma2(acc[3][1], d3, g.y);
            }
        }
    }

    const int y = ty0 + py;
    #pragma unroll
    for (int j = 0; j < 4; ++j) {
        const int xcol = tx0 + px0 + j;
        float bv[4];
        float2 p0 = unpk(acc[j][0]); bv[0] = p0.x; bv[1] = p0.y;
        float2 p1 = unpk(acc[j][1]); bv[2] = p1.x; bv[3] = p1.y;
        #pragma unroll
        for (int mm = 0; mm < 4; ++mm) {
            const size_t idx = ((size_t)(bi * 64 + m0 + mm) * H + y) * W + xcol;
            const float bb = bv[mm];
            const float un = 0.1f * bb;
            g_B[idx]  = bb;
            g_U[idx]  = un;
            g_A0[idx] = shrinkf(un);
        }
    }
}

// ---------------------------------------------------------------------------
// One LCA iteration, fused border correction.
// 128 threads; thread tile = 4 px (f32x2 over channel pairs) x 8 channels.
// 8 chunks of 8 input channels: gs[nl][tap][m] (18.4KB) + splatted a-halo
// asd[nl][10][12] as {v,v} ull (7.7KB) + corr buffers (4KB).
// ---------------------------------------------------------------------------
__global__ __launch_bounds__(128, 4)
void lca_iter(float* __restrict__ a_ext, int mode) {
    __shared__ float gs[8 * 9 * 64];                     // [nl][tap][m]
    __shared__ unsigned long long asd[8 * 10 * 12];      // [nl][r][c] splatted
    __shared__ float corrH[8][64];                       // [x-pos][m]
    __shared__ float corrV[8][64];                       // [y-pos][m]

    const float* __restrict__ a_in  = mode ? a_ext : g_A0;
    float* __restrict__       a_out = mode ? g_A0  : a_ext;

    const int bi   = blockIdx.y;
    const int tile = blockIdx.x;
    const int ty0  = (tile / 7) * 8, tx0 = (tile % 7) * 8;
    const int tid  = threadIdx.x;
    const int pg   = tid & 15, cg = tid >> 4;
    const int py   = pg >> 1, px0 = (pg & 1) * 4;
    const int m0   = cg * 8;

    const bool top = (ty0 == 0), bot = (ty0 == 48);
    const bool lef = (tx0 == 0), rig = (tx0 == 48);
    const bool hE = top || bot, vE = lef || rig;

    if (hE || vE) {
        for (int e = tid; e < 512; e += 128) {
            (&corrH[0][0])[e] = 0.0f;
            (&corrV[0][0])[e] = 0.0f;
        }
    }

    unsigned long long acc[4][4];
    #pragma unroll
    for (int j = 0; j < 4; ++j)
        #pragma unroll
        for (int c = 0; c < 4; ++c) acc[j][c] = 0ull;

    const float* abase = a_in + (size_t)bi * PLANE;

    for (int ck = 0; ck < 8; ++ck) {
        const int ch0 = ck * 8;
        __syncthreads();                                  // prev chunk done
        // G slice, transposed to [nl][tap][m]
        for (int e = tid; e < 8 * 9 * 64; e += 128) {
            const int m = e & 63, q = e >> 6;             // q = nl*9+tap
            const int nl = q / 9, tap = q - nl * 9;
            gs[e] = g_G[tap * 4096 + (ch0 + nl) * 64 + m];
        }
        // a halo (10x10, zero outside), splatted to both f32x2 halves
        for (int e = tid; e < 800; e += 128) {
            const int nl = e / 100, rr = (e / 10) % 10, cc = e % 10;
            const int gy = ty0 - 1 + rr, gx = tx0 - 1 + cc;
            float v = 0.0f;
            if ((unsigned)gy < (unsigned)H && (unsigned)gx < (unsigned)W)
                v = abase[(ch0 + nl) * HW + gy * W + gx];
            asd[nl * 120 + rr * 12 + cc] = dup2(v);
        }
        __syncthreads();

        for (int nl = 0; nl < 8; ++nl) {
            unsigned long long ar[3][6];
            const unsigned long long* ab = &asd[nl * 120 + py * 12 + px0];
            #pragma unroll
            for (int rw = 0; rw < 3; ++rw) {
                ulonglong2 p0 = *reinterpret_cast<const ulonglong2*>(ab + rw * 12 + 0);
                ulonglong2 p1 = *reinterpret_cast<const ulonglong2*>(ab + rw * 12 + 2);
                ulonglong2 p2 = *reinterpret_cast<const ulonglong2*>(ab + rw * 12 + 4);
                ar[rw][0] = p0.x; ar[rw][1] = p0.y;
                ar[rw][2] = p1.x; ar[rw][3] = p1.y;
                ar[rw][4] = p2.x; ar[rw][5] = p2.y;
            }
            const float* gp = &gs[nl * 576 + m0];
            #pragma unroll
            for (int tap = 0; tap < 9; ++tap) {
                const int ty_ = tap / 3, tx_ = tap % 3;
                ulonglong2 h0 = *reinterpret_cast<const ulonglong2*>(gp + tap * 64);
                ulonglong2 h1 = *reinterpret_cast<const ulonglong2*>(gp + tap * 64 + 4);
                #pragma unroll
                for (int j = 0; j < 4; ++j) {
                    const unsigned long long av = ar[2 - ty_][2 - tx_ + j];
                    ffma2(acc[j][0], av, h0.x);
                    ffma2(acc[j][1], av, h0.y);
                    ffma2(acc[j][2], av, h1.x);
                    ffma2(acc[j][3], av, h1.y);
                }
            }
        }

        // ---- border correction accumulation (tiny; reads asd lo-halves) ---
        if (hE) {
            const float* __restrict__ C = top ? g_CT : g_CB;
            const int er = top ? 1 : 8;
            const int m = tid >> 1, p0 = (tid & 1) * 4;
            float c0 = 0.f, c1 = 0.f, c2 = 0.f, c3 = 0.f;
            const float* al = reinterpret_cast<const float*>(asd);
            for (int j = 0; j < 3; ++j)
                #pragma unroll
                for (int nl = 0; nl < 8; ++nl) {
                    const float cv = C[j * 4096 + (ch0 + nl) * 64 + m];
                    const int base = 2 * (nl * 120 + er * 12 + p0 + 2 - j);
                    c0 += cv * al[base + 0];
                    c1 += cv * al[base + 2];
                    c2 += cv * al[base + 4];
                    c3 += cv * al[base + 6];
                }
            corrH[p0 + 0][m] += c0; corrH[p0 + 1][m] += c1;
            corrH[p0 + 2][m] += c2; corrH[p0 + 3][m] += c3;
        }
        if (vE) {
            const float* __restrict__ C = lef ? g_CL : g_CR;
            const int ec = lef ? 1 : 8;
            const int m = tid >> 1, p0 = (tid & 1) * 4;
            float c0 = 0.f, c1 = 0.f, c2 = 0.f, c3 = 0.f;
            const float* al = reinterpret_cast<const float*>(asd);
            for (int j = 0; j < 3; ++j)
                #pragma unroll
                for (int nl = 0; nl < 8; ++nl) {
                    const float cv = C[j * 4096 + (ch0 + nl) * 64 + m];
                    const int base = 2 * (nl * 120 + (p0 + 2 - j) * 12 + ec);
                    c0 += cv * al[base + 0 * 24];
                    c1 += cv * al[base + 1 * 24];
                    c2 += cv * al[base + 2 * 24];
                    c3 += cv * al[base + 3 * 24];
                }
            corrV[p0 + 0][m] += c0; corrV[p0 + 1][m] += c1;
            corrV[p0 + 2][m] += c2; corrV[p0 + 3][m] += c3;
        }
        if (hE && vE) {
            // corner overlap add-back: fold +CO into corrH at the corner pos
            const int m = tid >> 1;
            const int half = tid & 1;
            const int want = rig ? 1 : 0;                 // pos 0 -> half0, pos 7 -> half1
            if (half == want) {
                const int c = (top ? 0 : 2) + (rig ? 1 : 0);
                const int rr = top ? 1 : 8, cc = lef ? 1 : 8;
                const float* al = reinterpret_cast<const float*>(asd);
                float s = 0.f;
                #pragma unroll
                for (int nl = 0; nl < 8; ++nl)
                    s += g_CO[c * 4096 + (ch0 + nl) * 64 + m]
                       * al[2 * (nl * 120 + rr * 12 + cc)];
                corrH[rig ? 7 : 0][m] -= s;
            }
        }
    }
    __syncthreads();                                      // corr complete

    // ---- epilogue: fused u update + shrink ---------------------------------
    float ga[4][8];
    #pragma unroll
    for (int j = 0; j < 4; ++j)
        #pragma unroll
        for (int c = 0; c < 4; ++c) {
            float2 p = unpk(acc[j][c]);
            ga[j][2 * c] = p.x; ga[j][2 * c + 1] = p.y;
        }

    if ((top && py == 0) || (bot && py == 7)) {
        #pragma unroll
        for (int j = 0; j < 4; ++j)
            #pragma unroll
            for (int ch = 0; ch < 8; ++ch)
                ga[j][ch] -= corrH[px0 + j][m0 + ch];
    }
    if (lef && px0 == 0) {
        #pragma unroll
        for (int ch = 0; ch < 8; ++ch) ga[0][ch] -= corrV[py][m0 + ch];
    }
    if (rig && px0 == 4) {
        #pragma unroll
        for (int ch = 0; ch < 8; ++ch) ga[3][ch] -= corrV[py][m0 + ch];
    }

    const int y = ty0 + py;
    #pragma unroll
    for (int ch = 0; ch < 8; ++ch) {
        const size_t base =
            ((size_t)(bi * 64 + m0 + ch) * H + y) * W + tx0 + px0;
        float4 u4 = *reinterpret_cast<const float4*>(&g_U[base]);
        float4 b4 = *reinterpret_cast<const float4*>(&g_B[base]);
        float4 un, an;
        un.x = u4.x + 0.1f * (b4.x - u4.x - ga[0][ch]);
        un.y = u4.y + 0.1f * (b4.y - u4.y - ga[1][ch]);
        un.z = u4.z + 0.1f * (b4.z - u4.z - ga[2][ch]);
        un.w = u4.w + 0.1f * (b4.w - u4.w - ga[3][ch]);
        an.x = shrinkf(un.x); an.y = shrinkf(un.y);
        an.z = shrinkf(un.z); an.w = shrinkf(un.w);
        *reinterpret_cast<float4*>(&g_U[base])   = un;
        *reinterpret_cast<float4*>(&a_out[base]) = an;
    }
}

// ---------------------------------------------------------------------------
extern "C" void kernel_launch(void* const* d_in, const int* in_sizes, int n_in,
                              void* d_out, int out_size) {
    (void)in_sizes; (void)n_in; (void)out_size;
    const float* x    = (const float*)d_in[0];
    const float* dict = (const float*)d_in[1];
    float*       out  = (float*)d_out;

    lca_gram<<<25, 256>>>(dict);
    lca_b<<<dim3(49, 64), 256>>>(x, dict);

    // iterations 2..10; odd count -> final a lands in d_out
    for (int it = 0; it < 9; ++it)
        lca_iter<<<dim3(49, 64), 128>>>(out, it & 1);
}

// round 8
// speedup vs baseline: 1.1541x; 1.0360x over previous
#include <cuda_runtime.h>

// ---------------------------------------------------------------------------
// LCA layer on GB300.
//
// b = conv2d(x, D, s=4, p=2); 10x { inh = conv(convT(a)) - a;
//   u += 0.1*(b - u - inh); a = softshrink(u, 0.1) }
//
// conv∘convT == Gram operator: 3x3 taps, G[t][n][m] 64x64 per tap, center
// diag -1 folded. Boundary phantom products collapse to 1-D 3-tap edge Grams
// CT/CB/CL/CR + 4 corner overlaps CO (inclusion-exclusion), fused into
// lca_iter.
//
// lca_iter layout (v3): warp w owns m-chunk [16w,16w+16) -> G LDS are
// full-warp broadcasts (1 wavefront each). Lane = (py, x-pair); thread =
// 2 px x 16 m. a-halo stored as plain floats (stride 13), loaded LDS.32 and
// splatted to f32x2 via MOV (issue slack > wavefront slack).
// ---------------------------------------------------------------------------

#define NATOMS 64
#define BATCH  64
#define H 56
#define W 56
#define HW (H*W)
#define PLANE ((size_t)NATOMS * HW)

__device__ float g_B [BATCH * NATOMS * HW];
__device__ float g_U [BATCH * NATOMS * HW];
__device__ float g_A0[BATCH * NATOMS * HW];
__device__ float g_G [9 * 64 * 64];            // interior Gram [tap][n][m]
__device__ float g_CT[3 * 64 * 64];            // top edge, taps dx=-1,0,1
__device__ float g_CB[3 * 64 * 64];            // bottom
__device__ float g_CL[3 * 64 * 64];            // left,  taps dy=-1,0,1
__device__ float g_CR[3 * 64 * 64];            // right
__device__ float g_CO[4 * 64 * 64];            // corner overlaps TL,TR,BL,BR

// ---- packed f32x2 helpers --------------------------------------------------
__device__ __forceinline__ unsigned long long dup2(float x) {
    unsigned long long r;
    asm("mov.b64 %0, {%1, %1};" : "=l"(r) : "f"(x));
    return r;
}
__device__ __forceinline__ void ffma2(unsigned long long& d,
                                      unsigned long long a,
                                      unsigned long long b) {
    asm("fma.rn.f32x2 %0, %1, %2, %0;" : "+l"(d) : "l"(a), "l"(b));
}
__device__ __forceinline__ float2 unpk(unsigned long long v) {
    float2 r;
    asm("mov.b64 {%0, %1}, %2;" : "=f"(r.x), "=f"(r.y) : "l"(v));
    return r;
}
__device__ __forceinline__ float shrinkf(float u) {
    float mag = fabsf(u) - 0.1f;
    return mag > 0.0f ? copysignf(mag, u) : 0.0f;
}

// ---------------------------------------------------------------------------
// Gram kernel. 25 blocks: 0..8 interior taps, 9..20 edges, 21..24 corners.
// ---------------------------------------------------------------------------
__global__ void lca_gram(const float* __restrict__ dict) {
    __shared__ float ds[64 * 3 * 8 * 8];
    const int t   = blockIdx.x;
    const int tid = threadIdx.x;
    for (int e = tid; e < 12288; e += 256) ds[e] = dict[e];
    __syncthreads();

    if (t < 9) {
        const int dy = t / 3 - 1, dx = t % 3 - 1;
        const int kylo = dy < 0 ? 4 : 0, kyhi = dy > 0 ? 4 : 8;
        const int kxlo = dx < 0 ? 4 : 0, kxhi = dx > 0 ? 4 : 8;
        for (int e = tid; e < 4096; e += 256) {
            const int n = e >> 6, m = e & 63;
            float s = 0.0f;
            for (int i = 0; i < 3; ++i) {
                const float* dm = &ds[m * 192 + i * 64];
                const float* dn = &ds[n * 192 + i * 64 + 4 * dy * 8 + 4 * dx];
                for (int ky = kylo; ky < kyhi; ++ky)
                    #pragma unroll
                    for (int kx = kxlo; kx < kxhi; ++kx)
                        s += dm[ky * 8 + kx] * dn[ky * 8 + kx];
            }
            if (t == 4 && n == m) s -= 1.0f;
            g_G[t * 4096 + e] = s;
        }
    } else if (t < 21) {
        const int side = (t - 9) / 3;           // 0 top,1 bot,2 left,3 right
        const int j    = (t - 9) % 3;
        const int d    = j - 1;
        float* out = (side == 0 ? g_CT : side == 1 ? g_CB
                    : side == 2 ? g_CL : g_CR) + j * 4096;
        for (int e = tid; e < 4096; e += 256) {
            const int n = e >> 6, m = e & 63;
            float s = 0.0f;
            for (int i = 0; i < 3; ++i) {
                const float* dm = &ds[m * 192 + i * 64];
                const float* dn = &ds[n * 192 + i * 64];
                if (side < 2) {
                    const int ky0 = (side == 0) ? 0 : 6;
                    const int kxlo = d < 0 ? 4 : 0, kxhi = d > 0 ? 4 : 8;
                    for (int ky = ky0; ky < ky0 + 2; ++ky)
                        for (int kx = kxlo; kx < kxhi; ++kx)
                            s += dm[ky * 8 + kx] * dn[ky * 8 + kx + 4 * d];
                } else {
                    const int kx0 = (side == 2) ? 0 : 6;
                    const int kylo = d < 0 ? 4 : 0, kyhi = d > 0 ? 4 : 8;
                    for (int ky = kylo; ky < kyhi; ++ky)
                        for (int kx = kx0; kx < kx0 + 2; ++kx)
                            s += dm[ky * 8 + kx] * dn[(ky + 4 * d) * 8 + kx];
                }
            }
            out[e] = s;
        }
    } else {
        const int c   = t - 21;
        const int ky0 = (c < 2) ? 0 : 6;
        const int kx0 = (c & 1) ? 6 : 0;
        for (int e = tid; e < 4096; e += 256) {
            const int n = e >> 6, m = e & 63;
            float s = 0.0f;
            for (int i = 0; i < 3; ++i) {
                const float* dm = &ds[m * 192 + i * 64];
                const float* dn = &ds[n * 192 + i * 64];
                for (int ky = ky0; ky < ky0 + 2; ++ky)
                    for (int kx = kx0; kx < kx0 + 2; ++kx)
                        s += dm[ky * 8 + kx] * dn[ky * 8 + kx];
            }
            g_CO[c * 4096 + e] = s;
        }
    }
}

// ---------------------------------------------------------------------------
// b = conv2d(x, D, 4, 2), fused iter 1: u1 = 0.1*b, a1 = shrink(u1).
// ---------------------------------------------------------------------------
__global__ __launch_bounds__(256, 2)
void lca_b(const float* __restrict__ x, const float* __restrict__ dict) {
    __shared__ float xs[36 * 37];
    __shared__ float dt[64 * 64];

    const int bi   = blockIdx.y;
    const int tile = blockIdx.x;
    const int ty0  = (tile / 7) * 8, tx0 = (tile % 7) * 8;
    const int tid  = threadIdx.x;
    const int pg   = tid & 15, cg = tid >> 4;
    const int py   = pg >> 1, px0 = (pg & 1) * 4;
    const int m0   = cg * 4;

    unsigned long long acc[4][2];
    #pragma unroll
    for (int j = 0; j < 4; ++j) { acc[j][0] = 0ull; acc[j][1] = 0ull; }

    for (int i = 0; i < 3; ++i) {
        __syncthreads();
        for (int e = tid; e < 4096; e += 256) {
            const int kk = e >> 6, m = e & 63;
            dt[kk * 64 + m] = dict[m * 192 + i * 64 + kk];
        }
        const int gy0 = 4 * ty0 - 2, gx0 = 4 * tx0 - 2;
        for (int e = tid; e < 1296; e += 256) {
            const int r = e / 36, cc = e % 36;
            const int gy = gy0 + r, gx = gx0 + cc;
            float v = 0.0f;
            if ((unsigned)gy < 224u && (unsigned)gx < 224u)
                v = x[((size_t)(bi * 3 + i) * 224 + gy) * 224 + gx];
            xs[r * 37 + cc] = v;
        }
        __syncthreads();

        for (int ky = 0; ky < 8; ++ky) {
            const float* xr = &xs[(4 * py + ky) * 37 + 4 * px0];
            const float* dk = &dt[(ky * 8) * 64 + m0];
            #pragma unroll
            for (int kx = 0; kx < 8; ++kx) {
                ulonglong2 g = *reinterpret_cast<const ulonglong2*>(dk + kx * 64);
                const unsigned long long d0 = dup2(xr[0  + kx]);
                const unsigned long long d1 = dup2(xr[4  + kx]);
                const unsigned long long d2 = dup2(xr[8  + kx]);
                const unsigned long long d3 = dup2(xr[12 + kx]);
                ffma2(acc[0][0], d0, g.x); ffma2(acc[0][1], d0, g.y);
                ffma2(acc[1][0], d1, g.x); ffma2(acc[1][1], d1, g.y);
                ffma2(acc[2][0], d2, g.x); ffma2(acc[2][1], d2, g.y);
                ffma2(acc[3][0], d3, g.x); ffma2(acc[3][1], d3, g.y);
            }
        }
    }

    const int y = ty0 + py;
    #pragma unroll
    for (int j = 0; j < 4; ++j) {
        const int xcol = tx0 + px0 + j;
        float bv[4];
        float2 p0 = unpk(acc[j][0]); bv[0] = p0.x; bv[1] = p0.y;
        float2 p1 = unpk(acc[j][1]); bv[2] = p1.x; bv[3] = p1.y;
        #pragma unroll
        for (int mm = 0; mm < 4; ++mm) {
            const size_t idx = ((size_t)(bi * 64 + m0 + mm) * H + y) * W + xcol;
            const float bb = bv[mm];
            const float un = 0.1f * bb;
            g_B[idx]  = bb;
            g_U[idx]  = un;
            g_A0[idx] = shrinkf(un);
        }
    }
}

// ---------------------------------------------------------------------------
// One LCA iteration, fused border correction.
// 128 threads = 4 warps; warp w -> m-chunk m0 = 16w (warp-uniform G loads ->
// broadcast, 1 wavefront). Lane l -> py = l>>2, x-pair x0 = 2*(l&3).
// Thread tile: 2 px x 16 m (8 f32x2 acc pairs per px).
// 8 chunks of 8 input channels: gs[nl][tap][m] + float a-halo ash (stride 13).
// ---------------------------------------------------------------------------
__global__ __launch_bounds__(128, 4)
void lca_iter(float* __restrict__ a_ext, int mode) {
    __shared__ float gs [8 * 9 * 64];            // [nl][tap][m]   18.4 KB
    __shared__ float ash[8 * 10 * 13];           // [nl][r][c]      4.2 KB
    __shared__ float corrH[8][64];               // [x-pos][m]
    __shared__ float corrV[8][64];               // [y-pos][m]

    const float* __restrict__ a_in  = mode ? a_ext : g_A0;
    float* __restrict__       a_out = mode ? g_A0  : a_ext;

    const int bi   = blockIdx.y;
    const int tile = blockIdx.x;
    const int ty0  = (tile / 7) * 8, tx0 = (tile % 7) * 8;
    const int tid  = threadIdx.x;
    const int w    = tid >> 5, l = tid & 31;
    const int m0   = w * 16;
    const int py   = l >> 2, x0 = (l & 3) * 2;

    const bool top = (ty0 == 0), bot = (ty0 == 48);
    const bool lef = (tx0 == 0), rig = (tx0 == 48);
    const bool hE = top || bot, vE = lef || rig;

    if (hE || vE) {
        for (int e = tid; e < 512; e += 128) {
            (&corrH[0][0])[e] = 0.0f;
            (&corrV[0][0])[e] = 0.0f;
        }
    }

    unsigned long long acc[2][8];
    #pragma unroll
    for (int p = 0; p < 2; ++p)
        #pragma unroll
        for (int c = 0; c < 8; ++c) acc[p][c] = 0ull;

    const float* abase = a_in + (size_t)bi * PLANE;

    for (int ck = 0; ck < 8; ++ck) {
        const int ch0 = ck * 8;
        __syncthreads();                              // prev chunk consumed
        // G slice transposed to [nl][tap][m]
        for (int e = tid; e < 4608; e += 128) {
            const int m = e & 63, q = e >> 6;         // q = nl*9+tap
            const int nl = q / 9, tap = q - nl * 9;
            gs[e] = g_G[tap * 4096 + (ch0 + nl) * 64 + m];
        }
        // a halo (10x10 per channel, zero outside), plain floats, stride 13
        for (int e = tid; e < 800; e += 128) {
            const int nl = e / 100, r2 = e - nl * 100;
            const int rr = r2 / 10, cc = r2 - rr * 10;
            const int gy = ty0 - 1 + rr, gx = tx0 - 1 + cc;
            float v = 0.0f;
            if ((unsigned)gy < (unsigned)H && (unsigned)gx < (unsigned)W)
                v = abase[(ch0 + nl) * HW + gy * W + gx];
            ash[nl * 130 + rr * 13 + cc] = v;
        }
        __syncthreads();

        for (int nl = 0; nl < 8; ++nl) {
            // 3x4 a patch, splatted to f32x2 via MOV
            const float* ap = &ash[nl * 130 + py * 13 + x0];
            unsigned long long av[3][4];
            #pragma unroll
            for (int r = 0; r < 3; ++r)
                #pragma unroll
                for (int c = 0; c < 4; ++c)
                    av[r][c] = dup2(ap[r * 13 + c]);

            const float* gp = &gs[nl * 576 + m0];
            #pragma unroll
            for (int tap = 0; tap < 9; ++tap) {
                const int ty_ = tap / 3, tx_ = tap % 3;
                const float* gt = gp + tap * 64;      // warp-uniform address
                ulonglong2 H0 = *reinterpret_cast<const ulonglong2*>(gt + 0);
                ulonglong2 H1 = *reinterpret_cast<const ulonglong2*>(gt + 4);
                ulonglong2 H2 = *reinterpret_cast<const ulonglong2*>(gt + 8);
                ulonglong2 H3 = *reinterpret_cast<const ulonglong2*>(gt + 12);
                #pragma unroll
                for (int p = 0; p < 2; ++p) {
                    const unsigned long long a = av[2 - ty_][p + 2 - tx_];
                    ffma2(acc[p][0], a, H0.x); ffma2(acc[p][1], a, H0.y);
                    ffma2(acc[p][2], a, H1.x); ffma2(acc[p][3], a, H1.y);
                    ffma2(acc[p][4], a, H2.x); ffma2(acc[p][5], a, H2.y);
                    ffma2(acc[p][6], a, H3.x); ffma2(acc[p][7], a, H3.y);
                }
            }
        }

        // ---- border correction accumulation (edge blocks only) ------------
        if (hE) {
            const float* __restrict__ C = top ? g_CT : g_CB;
            const int er = top ? 1 : 8;
            const int m = tid >> 1, p0 = (tid & 1) * 4;
            float c0 = 0.f, c1 = 0.f, c2 = 0.f, c3 = 0.f;
            for (int j = 0; j < 3; ++j)
                #pragma unroll
                for (int nl = 0; nl < 8; ++nl) {
                    const float cv = C[j * 4096 + (ch0 + nl) * 64 + m];
                    const float* arow = &ash[nl * 130 + er * 13 + p0 + 2 - j];
                    c0 += cv * arow[0];
                    c1 += cv * arow[1];
                    c2 += cv * arow[2];
                    c3 += cv * arow[3];
                }
            corrH[p0 + 0][m] += c0; corrH[p0 + 1][m] += c1;
            corrH[p0 + 2][m] += c2; corrH[p0 + 3][m] += c3;
        }
        if (vE) {
            const float* __restrict__ C = lef ? g_CL : g_CR;
            const int ec = lef ? 1 : 8;
            const int m = tid >> 1, p0 = (tid & 1) * 4;
            float c0 = 0.f, c1 = 0.f, c2 = 0.f, c3 = 0.f;
            for (int j = 0; j < 3; ++j)
                #pragma unroll
                for (int nl = 0; nl < 8; ++nl) {
                    const float cv = C[j * 4096 + (ch0 + nl) * 64 + m];
                    const float* acol = &ash[nl * 130 + (p0 + 2 - j) * 13 + ec];
                    c0 += cv * acol[0];
                    c1 += cv * acol[13];
                    c2 += cv * acol[26];
                    c3 += cv * acol[39];
                }
            corrV[p0 + 0][m] += c0; corrV[p0 + 1][m] += c1;
            corrV[p0 + 2][m] += c2; corrV[p0 + 3][m] += c3;
        }
        if (hE && vE) {
            const int m = tid >> 1;
            const int half = tid & 1;
            const int want = rig ? 1 : 0;
            if (half == want) {
                const int c = (top ? 0 : 2) + (rig ? 1 : 0);
                const int rr = top ? 1 : 8, cc2 = lef ? 1 : 8;
                float s = 0.f;
                #pragma unroll
                for (int nl = 0; nl < 8; ++nl)
                    s += g_CO[c * 4096 + (ch0 + nl) * 64 + m]
                       * ash[nl * 130 + rr * 13 + cc2];
                corrH[rig ? 7 : 0][m] -= s;
            }
        }
    }
    __syncthreads();                                  // corr complete

    // ---- epilogue: fused u update + shrink ---------------------------------
    float ga[2][16];
    #pragma unroll
    for (int p = 0; p < 2; ++p)
        #pragma unroll
        for (int c = 0; c < 8; ++c) {
            float2 t = unpk(acc[p][c]);
            ga[p][2 * c] = t.x; ga[p][2 * c + 1] = t.y;
        }

    if ((top && py == 0) || (bot && py == 7)) {
        #pragma unroll
        for (int p = 0; p < 2; ++p)
            #pragma unroll
            for (int mi = 0; mi < 16; ++mi)
                ga[p][mi] -= corrH[x0 + p][m0 + mi];
    }
    if (lef && x0 == 0) {
        #pragma unroll
        for (int mi = 0; mi < 16; ++mi) ga[0][mi] -= corrV[py][m0 + mi];
    }
    if (rig && x0 == 6) {
        #pragma unroll
        for (int mi = 0; mi < 16; ++mi) ga[1][mi] -= corrV[py][m0 + mi];
    }

    const int y = ty0 + py, x = tx0 + x0;
    #pragma unroll
    for (int mi = 0; mi < 16; ++mi) {
        const size_t base = ((size_t)(bi * 64 + m0 + mi) * H + y) * W + x;
        float2 u2 = *reinterpret_cast<const float2*>(&g_U[base]);
        float2 b2 = *reinterpret_cast<const float2*>(&g_B[base]);
        float2 un, an;
        un.x = u2.x + 0.1f * (b2.x - u2.x - ga[0][mi]);
        un.y = u2.y + 0.1f * (b2.y - u2.y - ga[1][mi]);
        an.x = shrinkf(un.x); an.y = shrinkf(un.y);
        *reinterpret_cast<float2*>(&g_U[base])   = un;
        *reinterpret_cast<float2*>(&a_out[base]) = an;
    }
}

// ---------------------------------------------------------------------------
extern "C" void kernel_launch(void* const* d_in, const int* in_sizes, int n_in,
                              void* d_out, int out_size) {
    (void)in_sizes; (void)n_in; (void)out_size;
    const float* x    = (const float*)d_in[0];
    const float* dict = (const float*)d_in[1];
    float*       out  = (float*)d_out;

    lca_gram<<<25, 256>>>(dict);
    lca_b<<<dim3(49, 64), 256>>>(x, dict);

    // iterations 2..10; odd count -> final a lands in d_out
    for (int it = 0; it < 9; ++it)
        lca_iter<<<dim3(49, 64), 128>>>(out, it & 1);
}

// round 9
// speedup vs baseline: 1.3900x; 1.2044x over previous
#include <cuda_runtime.h>

// ---------------------------------------------------------------------------
// LCA layer on GB300.
//
// b = conv2d(x, D, s=4, p=2); 10x { inh = conv(convT(a)) - a;
//   u += 0.1*(b - u - inh); a = softshrink(u, 0.1) }
//
// conv∘convT == Gram operator: 3x3 taps, G[t][n][m] 64x64 per tap, center
// diag -1 folded. Boundary phantom products collapse to 1-D 3-tap edge Grams
// CT/CB/CL/CR + 4 corner overlaps CO (inclusion-exclusion), fused into
// lca_iter.
//
// lca_iter (v4): block tile 8x16 px (4 col-tiles over 56, last predicated),
// 128 thr / 4 warps, warp w -> m-chunk 16w (warp-uniform G -> broadcast),
// thread = 4 px x 16 m so each G LDS.128 feeds 8 FFMA2 (2x v3) -> crossbar
// drops below fma. gs staged via float4; a-halo stride 21 (conflict-free).
// ---------------------------------------------------------------------------

#define NATOMS 64
#define BATCH  64
#define H 56
#define W 56
#define HW (H*W)
#define PLANE ((size_t)NATOMS * HW)

__device__ float g_B [BATCH * NATOMS * HW];
__device__ float g_U [BATCH * NATOMS * HW];
__device__ float g_A0[BATCH * NATOMS * HW];
__device__ float g_G [9 * 64 * 64];            // interior Gram [tap][n][m]
__device__ float g_CT[3 * 64 * 64];            // top edge, taps dx=-1,0,1
__device__ float g_CB[3 * 64 * 64];            // bottom
__device__ float g_CL[3 * 64 * 64];            // left,  taps dy=-1,0,1
__device__ float g_CR[3 * 64 * 64];            // right
__device__ float g_CO[4 * 64 * 64];            // corner overlaps TL,TR,BL,BR

// ---- packed f32x2 helpers --------------------------------------------------
__device__ __forceinline__ unsigned long long dup2(float x) {
    unsigned long long r;
    asm("mov.b64 %0, {%1, %1};" : "=l"(r) : "f"(x));
    return r;
}
__device__ __forceinline__ void ffma2(unsigned long long& d,
                                      unsigned long long a,
                                      unsigned long long b) {
    asm("fma.rn.f32x2 %0, %1, %2, %0;" : "+l"(d) : "l"(a), "l"(b));
}
__device__ __forceinline__ float2 unpk(unsigned long long v) {
    float2 r;
    asm("mov.b64 {%0, %1}, %2;" : "=f"(r.x), "=f"(r.y) : "l"(v));
    return r;
}
__device__ __forceinline__ float shrinkf(float u) {
    float mag = fabsf(u) - 0.1f;
    return mag > 0.0f ? copysignf(mag, u) : 0.0f;
}

// ---------------------------------------------------------------------------
// Gram kernel. 25 blocks: 0..8 interior taps, 9..20 edges, 21..24 corners.
// ---------------------------------------------------------------------------
__global__ void lca_gram(const float* __restrict__ dict) {
    __shared__ float ds[64 * 3 * 8 * 8];
    const int t   = blockIdx.x;
    const int tid = threadIdx.x;
    for (int e = tid; e < 12288; e += 256) ds[e] = dict[e];
    __syncthreads();

    if (t < 9) {
        const int dy = t / 3 - 1, dx = t % 3 - 1;
        const int kylo = dy < 0 ? 4 : 0, kyhi = dy > 0 ? 4 : 8;
        const int kxlo = dx < 0 ? 4 : 0, kxhi = dx > 0 ? 4 : 8;
        for (int e = tid; e < 4096; e += 256) {
            const int n = e >> 6, m = e & 63;
            float s = 0.0f;
            for (int i = 0; i < 3; ++i) {
                const float* dm = &ds[m * 192 + i * 64];
                const float* dn = &ds[n * 192 + i * 64 + 4 * dy * 8 + 4 * dx];
                for (int ky = kylo; ky < kyhi; ++ky)
                    #pragma unroll
                    for (int kx = kxlo; kx < kxhi; ++kx)
                        s += dm[ky * 8 + kx] * dn[ky * 8 + kx];
            }
            if (t == 4 && n == m) s -= 1.0f;
            g_G[t * 4096 + e] = s;
        }
    } else if (t < 21) {
        const int side = (t - 9) / 3;           // 0 top,1 bot,2 left,3 right
        const int j    = (t - 9) % 3;
        const int d    = j - 1;
        float* out = (side == 0 ? g_CT : side == 1 ? g_CB
                    : side == 2 ? g_CL : g_CR) + j * 4096;
        for (int e = tid; e < 4096; e += 256) {
            const int n = e >> 6, m = e & 63;
            float s = 0.0f;
            for (int i = 0; i < 3; ++i) {
                const float* dm = &ds[m * 192 + i * 64];
                const float* dn = &ds[n * 192 + i * 64];
                if (side < 2) {
                    const int ky0 = (side == 0) ? 0 : 6;
                    const int kxlo = d < 0 ? 4 : 0, kxhi = d > 0 ? 4 : 8;
                    for (int ky = ky0; ky < ky0 + 2; ++ky)
                        for (int kx = kxlo; kx < kxhi; ++kx)
                            s += dm[ky * 8 + kx] * dn[ky * 8 + kx + 4 * d];
                } else {
                    const int kx0 = (side == 2) ? 0 : 6;
                    const int kylo = d < 0 ? 4 : 0, kyhi = d > 0 ? 4 : 8;
                    for (int ky = kylo; ky < kyhi; ++ky)
                        for (int kx = kx0; kx < kx0 + 2; ++kx)
                            s += dm[ky * 8 + kx] * dn[(ky + 4 * d) * 8 + kx];
                }
            }
            out[e] = s;
        }
    } else {
        const int c   = t - 21;
        const int ky0 = (c < 2) ? 0 : 6;
        const int kx0 = (c & 1) ? 6 : 0;
        for (int e = tid; e < 4096; e += 256) {
            const int n = e >> 6, m = e & 63;
            float s = 0.0f;
            for (int i = 0; i < 3; ++i) {
                const float* dm = &ds[m * 192 + i * 64];
                const float* dn = &ds[n * 192 + i * 64];
                for (int ky = ky0; ky < ky0 + 2; ++ky)
                    for (int kx = kx0; kx < kx0 + 2; ++kx)
                        s += dm[ky * 8 + kx] * dn[ky * 8 + kx];
            }
            g_CO[c * 4096 + e] = s;
        }
    }
}

// ---------------------------------------------------------------------------
// b = conv2d(x, D, 4, 2), fused iter 1: u1 = 0.1*b, a1 = shrink(u1).
// ---------------------------------------------------------------------------
__global__ __launch_bounds__(256, 2)
void lca_b(const float* __restrict__ x, const float* __restrict__ dict) {
    __shared__ float xs[36 * 37];
    __shared__ float dt[64 * 64];

    const int bi   = blockIdx.y;
    const int tile = blockIdx.x;
    const int ty0  = (tile / 7) * 8, tx0 = (tile % 7) * 8;
    const int tid  = threadIdx.x;
    const int pg   = tid & 15, cg = tid >> 4;
    const int py   = pg >> 1, px0 = (pg & 1) * 4;
    const int m0   = cg * 4;

    unsigned long long acc[4][2];
    #pragma unroll
    for (int j = 0; j < 4; ++j) { acc[j][0] = 0ull; acc[j][1] = 0ull; }

    for (int i = 0; i < 3; ++i) {
        __syncthreads();
        for (int e = tid; e < 4096; e += 256) {
            const int kk = e >> 6, m = e & 63;
            dt[kk * 64 + m] = dict[m * 192 + i * 64 + kk];
        }
        const int gy0 = 4 * ty0 - 2, gx0 = 4 * tx0 - 2;
        for (int e = tid; e < 1296; e += 256) {
            const int r = e / 36, cc = e % 36;
            const int gy = gy0 + r, gx = gx0 + cc;
            float v = 0.0f;
            if ((unsigned)gy < 224u && (unsigned)gx < 224u)
                v = x[((size_t)(bi * 3 + i) * 224 + gy) * 224 + gx];
            xs[r * 37 + cc] = v;
        }
        __syncthreads();

        for (int ky = 0; ky < 8; ++ky) {
            const float* xr = &xs[(4 * py + ky) * 37 + 4 * px0];
            const float* dk = &dt[(ky * 8) * 64 + m0];
            #pragma unroll
            for (int kx = 0; kx < 8; ++kx) {
                ulonglong2 g = *reinterpret_cast<const ulonglong2*>(dk + kx * 64);
                const unsigned long long d0 = dup2(xr[0  + kx]);
                const unsigned long long d1 = dup2(xr[4  + kx]);
                const unsigned long long d2 = dup2(xr[8  + kx]);
                const unsigned long long d3 = dup2(xr[12 + kx]);
                ffma2(acc[0][0], d0, g.x); ffma2(acc[0][1], d0, g.y);
                ffma2(acc[1][0], d1, g.x); ffma2(acc[1][1], d1, g.y);
                ffma2(acc[2][0], d2, g.x); ffma2(acc[2][1], d2, g.y);
                ffma2(acc[3][0], d3, g.x); ffma2(acc[3][1], d3, g.y);
            }
        }
    }

    const int y = ty0 + py;
    #pragma unroll
    for (int j = 0; j < 4; ++j) {
        const int xcol = tx0 + px0 + j;
        float bv[4];
        float2 p0 = unpk(acc[j][0]); bv[0] = p0.x; bv[1] = p0.y;
        float2 p1 = unpk(acc[j][1]); bv[2] = p1.x; bv[3] = p1.y;
        #pragma unroll
        for (int mm = 0; mm < 4; ++mm) {
            const size_t idx = ((size_t)(bi * 64 + m0 + mm) * H + y) * W + xcol;
            const float bb = bv[mm];
            const float un = 0.1f * bb;
            g_B[idx]  = bb;
            g_U[idx]  = un;
            g_A0[idx] = shrinkf(un);
        }
    }
}

// ---------------------------------------------------------------------------
// One LCA iteration, fused border correction.
// Block tile: 8 rows x 16 cols (4 col-tiles: x starts 0,16,32,48; quads at
// x>=56 fully predicated). 128 thr / 4 warps; warp w -> m0=16w (uniform G).
// Lane l: py = l>>2, xq = l&3 (x0 = 4*xq). Thread: 4 px x 16 m.
// 8 chunks of 8 input channels; gs[nl][tap][m] (float4-staged), a-halo
// ash[nl][10][18] stride 21 (conflict-free for this lane map).
// ---------------------------------------------------------------------------
__global__ __launch_bounds__(128, 3)
void lca_iter(float* __restrict__ a_ext, int mode) {
    __shared__ float gs [8 * 9 * 64];            // [nl*9+tap][m]   18.4 KB
    __shared__ float ash[8 * 10 * 21];           // [nl][r][c<18]    6.7 KB
    __shared__ float corrH[16][64];              // [local x][m]     4.0 KB
    __shared__ float corrV[8][64];               // [py][m]          2.0 KB

    const float* __restrict__ a_in  = mode ? a_ext : g_A0;
    float* __restrict__       a_out = mode ? g_A0  : a_ext;

    const int bi   = blockIdx.y;
    const int tile = blockIdx.x;                 // 0..27
    const int ty0  = (tile >> 2) * 8;
    const int tx0  = (tile & 3) * 16;
    const int tid  = threadIdx.x;
    const int w    = tid >> 5, l = tid & 31;
    const int m0   = w * 16;
    const int py   = l >> 2, xq = l & 3, x0 = 4 * xq;

    const bool top = (ty0 == 0), bot = (ty0 == 48);
    const bool lef = (tx0 == 0), rig = (tx0 == 48);
    const bool hE = top || bot, vE = lef || rig;

    if (hE || vE) {
        for (int e = tid; e < 1024; e += 128) (&corrH[0][0])[e] = 0.0f;
        for (int e = tid; e < 512;  e += 128) (&corrV[0][0])[e] = 0.0f;
    }

    unsigned long long acc[4][8];
    #pragma unroll
    for (int j = 0; j < 4; ++j)
        #pragma unroll
        for (int c = 0; c < 8; ++c) acc[j][c] = 0ull;

    const float* abase = a_in + (size_t)bi * PLANE;

    for (int ck = 0; ck < 8; ++ck) {
        const int ch0 = ck * 8;
        __syncthreads();                              // prev chunk consumed
        // G slice [nl*9+tap][m], float4-staged (rows contiguous both sides)
        for (int e = tid; e < 1152; e += 128) {
            const int m4 = e & 15, q = e >> 4;        // q = nl*9+tap
            const int nl = q / 9, tap = q - nl * 9;
            reinterpret_cast<float4*>(gs)[e] =
                reinterpret_cast<const float4*>(
                    g_G + tap * 4096 + (ch0 + nl) * 64)[m4];
        }
        // a halo: 10 rows x 18 cols per channel, zero outside image
        for (int e = tid; e < 1440; e += 128) {
            const int nl = e / 180, r2 = e - nl * 180;
            const int rr = r2 / 18, cc = r2 - rr * 18;
            const int gy = ty0 - 1 + rr, gx = tx0 - 1 + cc;
            float v = 0.0f;
            if ((unsigned)gy < (unsigned)H && (unsigned)gx < (unsigned)W)
                v = abase[(ch0 + nl) * HW + gy * W + gx];
            ash[nl * 210 + rr * 21 + cc] = v;
        }
        __syncthreads();

        for (int nl = 0; nl < 8; ++nl) {
            // 3x6 a patch, splatted to f32x2
            const float* ap = &ash[nl * 210 + py * 21 + x0];
            unsigned long long av[3][6];
            #pragma unroll
            for (int r = 0; r < 3; ++r)
                #pragma unroll
                for (int c = 0; c < 6; ++c)
                    av[r][c] = dup2(ap[r * 21 + c]);

            const float* gp = &gs[nl * 576 + m0];
            #pragma unroll
            for (int tap = 0; tap < 9; ++tap) {
                const int ty_ = tap / 3, tx_ = tap % 3;
                const float* gt = gp + tap * 64;      // warp-uniform address
                ulonglong2 H0 = *reinterpret_cast<const ulonglong2*>(gt + 0);
                ulonglong2 H1 = *reinterpret_cast<const ulonglong2*>(gt + 4);
                ulonglong2 H2 = *reinterpret_cast<const ulonglong2*>(gt + 8);
                ulonglong2 H3 = *reinterpret_cast<const ulonglong2*>(gt + 12);
                #pragma unroll
                for (int j = 0; j < 4; ++j) {
                    const unsigned long long a = av[2 - ty_][j + 2 - tx_];
                    ffma2(acc[j][0], a, H0.x); ffma2(acc[j][1], a, H0.y);
                    ffma2(acc[j][2], a, H1.x); ffma2(acc[j][3], a, H1.y);
                    ffma2(acc[j][4], a, H2.x); ffma2(acc[j][5], a, H2.y);
                    ffma2(acc[j][6], a, H3.x); ffma2(acc[j][7], a, H3.y);
                }
            }
        }

        // ---- border correction accumulation (edge blocks only) ------------
        if (hE) {
            const float* __restrict__ C = top ? g_CT : g_CB;
            const int er = top ? 1 : 8;
            const int m = tid >> 1, p0 = (tid & 1) * 8;
            float c[8];
            #pragma unroll
            for (int k = 0; k < 8; ++k) c[k] = 0.0f;
            for (int j = 0; j < 3; ++j)
                #pragma unroll
                for (int nl = 0; nl < 8; ++nl) {
                    const float cv = C[j * 4096 + (ch0 + nl) * 64 + m];
                    const float* arow = &ash[nl * 210 + er * 21 + p0 + 2 - j];
                    #pragma unroll
                    for (int k = 0; k < 8; ++k) c[k] += cv * arow[k];
                }
            #pragma unroll
            for (int k = 0; k < 8; ++k) corrH[p0 + k][m] += c[k];
        }
        if (vE) {
            const float* __restrict__ C = lef ? g_CL : g_CR;
            const int ec = lef ? 1 : 8;
            const int m = tid >> 1, p0 = (tid & 1) * 4;
            float c0 = 0.f, c1 = 0.f, c2 = 0.f, c3 = 0.f;
            for (int j = 0; j < 3; ++j)
                #pragma unroll
                for (int nl = 0; nl < 8; ++nl) {
                    const float cv = C[j * 4096 + (ch0 + nl) * 64 + m];
                    const float* acol = &ash[nl * 210 + (p0 + 2 - j) * 21 + ec];
                    c0 += cv * acol[0];
                    c1 += cv * acol[21];
                    c2 += cv * acol[42];
                    c3 += cv * acol[63];
                }
            corrV[p0 + 0][m] += c0; corrV[p0 + 1][m] += c1;
            corrV[p0 + 2][m] += c2; corrV[p0 + 3][m] += c3;
        }
        if (hE && vE) {
            const int m = tid >> 1;
            const int half = tid & 1;
            const int want = rig ? 1 : 0;
            if (half == want) {
                const int c = (top ? 0 : 2) + (rig ? 1 : 0);
                const int rr = top ? 1 : 8, cc2 = lef ? 1 : 8;
                float s = 0.f;
                #pragma unroll
                for (int nl = 0; nl < 8; ++nl)
                    s += g_CO[c * 4096 + (ch0 + nl) * 64 + m]
                       * ash[nl * 210 + rr * 21 + cc2];
                corrH[rig ? 7 : 0][m] -= s;
            }
        }
    }
    __syncthreads();                                  // corr complete

    // ---- epilogue: fused u update + shrink ---------------------------------
    const int xg = tx0 + x0;                          // global x of quad start
    if (xg < 56) {
        float ga[4][16];
        #pragma unroll
        for (int j = 0; j < 4; ++j)
            #pragma unroll
            for (int c = 0; c < 8; ++c) {
                float2 t = unpk(acc[j][c]);
                ga[j][2 * c] = t.x; ga[j][2 * c + 1] = t.y;
            }

        if ((top && py == 0) || (bot && py == 7)) {
            #pragma unroll
            for (int j = 0; j < 4; ++j)
                #pragma unroll
                for (int mi = 0; mi < 16; ++mi)
                    ga[j][mi] -= corrH[x0 + j][m0 + mi];
        }
        if (lef && xq == 0) {
            #pragma unroll
            for (int mi = 0; mi < 16; ++mi) ga[0][mi] -= corrV[py][m0 + mi];
        }
        if (rig && xq == 1) {                         // local x 7 = global 55
            #pragma unroll
            for (int mi = 0; mi < 16; ++mi) ga[3][mi] -= corrV[py][m0 + mi];
        }

        const int y = ty0 + py;
        #pragma unroll
        for (int mi = 0; mi < 16; ++mi) {
            const size_t base = ((size_t)(bi * 64 + m0 + mi) * H + y) * W + xg;
            float4 u4 = *reinterpret_cast<const float4*>(&g_U[base]);
            float4 b4 = *reinterpret_cast<const float4*>(&g_B[base]);
            float4 un, an;
            un.x = u4.x + 0.1f * (b4.x - u4.x - ga[0][mi]);
            un.y = u4.y + 0.1f * (b4.y - u4.y - ga[1][mi]);
            un.z = u4.z + 0.1f * (b4.z - u4.z - ga[2][mi]);
            un.w = u4.w + 0.1f * (b4.w - u4.w - ga[3][mi]);
            an.x = shrinkf(un.x); an.y = shrinkf(un.y);
            an.z = shrinkf(un.z); an.w = shrinkf(un.w);
            *reinterpret_cast<float4*>(&g_U[base])   = un;
            *reinterpret_cast<float4*>(&a_out[base]) = an;
        }
    }
}

// ---------------------------------------------------------------------------
extern "C" void kernel_launch(void* const* d_in, const int* in_sizes, int n_in,
                              void* d_out, int out_size) {
    (void)in_sizes; (void)n_in; (void)out_size;
    const float* x    = (const float*)d_in[0];
    const float* dict = (const float*)d_in[1];
    float*       out  = (float*)d_out;

    lca_gram<<<25, 256>>>(dict);
    lca_b<<<dim3(49, 64), 256>>>(x, dict);

    // iterations 2..10; odd count -> final a lands in d_out
    for (int it = 0; it < 9; ++it)
        lca_iter<<<dim3(28, 64), 128>>>(out, it & 1);
}